// round 7
// baseline (speedup 1.0000x reference)
#include <cuda_runtime.h>
#include <math.h>
#include <stdint.h>

// ---------------- problem constants ----------------
#define NU   50000
#define NM   20000
#define NRV  200000
#define NALL 270000
#define HIDC 256
#define NE   200000
#define NH   8
#define HD   32
#define LRS  0.01f   // leaky relu slope

// ---------------- device scratch (no allocations allowed) ----------------
__device__ float g_xs [(size_t)NALL * HIDC];
__device__ float g_K  [(size_t)NALL * HIDC];
__device__ float g_Q  [(size_t)NALL * HIDC];
__device__ float g_V  [(size_t)NALL * HIDC];
__device__ float g_out[(size_t)NALL * HIDC];
__device__ float g_krel[(size_t)NRV * HIDC];
__device__ float g_vrel[(size_t)NRV * HIDC];
__device__ float g_logits[(size_t)NE * NH];
__device__ unsigned g_amax[(size_t)NALL * NH];
__device__ float g_den [(size_t)NALL * NH];

// order-preserving float<->uint mapping for atomicMax on floats
__device__ __forceinline__ unsigned f2u_ord(float f) {
    unsigned u = __float_as_uint(f);
    return (u & 0x80000000u) ? ~u : (u | 0x80000000u);
}
__device__ __forceinline__ float u2f_ord(unsigned u) {
    return (u & 0x80000000u) ? __uint_as_float(u & 0x7fffffffu)
                             : __uint_as_float(~u);
}

// ---------------- generic SGEMM: C[M,N] = A[M,K] * B[K,N] + bias, act ----------------
// BM=128, BN=64, BK=16, 256 threads, each thread 8x4.
// Requires N % 64 == 0, K % 16 == 0 (true for all call sites). M guarded.
__global__ __launch_bounds__(256) void sgemm_kernel(
    const float* __restrict__ A, const float* __restrict__ B,
    const float* __restrict__ bias, float* __restrict__ C,
    int M, int N, int K, int act)
{
    __shared__ float As[16][128];   // [k][m] (transposed)
    __shared__ float Bs[16][64];    // [k][n]

    int tid = threadIdx.x;
    int tx  = tid & 15;             // n group
    int ty  = tid >> 4;             // m group
    int m0  = blockIdx.y * 128;
    int n0  = blockIdx.x * 64;

    float acc[8][4];
#pragma unroll
    for (int i = 0; i < 8; i++)
#pragma unroll
        for (int j = 0; j < 4; j++) acc[i][j] = 0.f;

    for (int k0 = 0; k0 < K; k0 += 16) {
        // A tile: 128x16 = 512 float4, 2 per thread
#pragma unroll
        for (int i = 0; i < 2; i++) {
            int f   = tid + i * 256;        // 0..511
            int row = f >> 2;               // 0..127
            int c4  = f & 3;                // 0..3
            float4 v = make_float4(0.f, 0.f, 0.f, 0.f);
            if (m0 + row < M)
                v = *(const float4*)(A + (size_t)(m0 + row) * K + k0 + c4 * 4);
            As[c4 * 4 + 0][row] = v.x;
            As[c4 * 4 + 1][row] = v.y;
            As[c4 * 4 + 2][row] = v.z;
            As[c4 * 4 + 3][row] = v.w;
        }
        // B tile: 16x64 = 256 float4, 1 per thread
        {
            int r  = tid >> 4;
            int c4 = tid & 15;
            float4 v = *(const float4*)(B + (size_t)(k0 + r) * N + n0 + c4 * 4);
            *(float4*)&Bs[r][c4 * 4] = v;
        }
        __syncthreads();

#pragma unroll
        for (int kk = 0; kk < 16; kk++) {
            float4 a0 = *(float4*)&As[kk][ty * 8];
            float4 a1 = *(float4*)&As[kk][ty * 8 + 4];
            float4 b  = *(float4*)&Bs[kk][tx * 4];
            float am[8] = {a0.x, a0.y, a0.z, a0.w, a1.x, a1.y, a1.z, a1.w};
            float bn[4] = {b.x, b.y, b.z, b.w};
#pragma unroll
            for (int i = 0; i < 8; i++)
#pragma unroll
                for (int j = 0; j < 4; j++)
                    acc[i][j] += am[i] * bn[j];
        }
        __syncthreads();
    }

    float bv[4];
#pragma unroll
    for (int j = 0; j < 4; j++) bv[j] = bias[n0 + tx * 4 + j];

#pragma unroll
    for (int i = 0; i < 8; i++) {
        int row = m0 + ty * 8 + i;
        if (row < M) {
            float t[4];
#pragma unroll
            for (int j = 0; j < 4; j++) {
                float v = acc[i][j] + bv[j];
                if (act == 1) v = (v > 0.f) ? v : LRS * v;   // leaky relu
                t[j] = v;
            }
            *(float4*)(C + (size_t)row * N + n0 + tx * 4) =
                make_float4(t[0], t[1], t[2], t[3]);
        }
    }
}

// ---------------- per-head relation transform: Y[n,h,:] = X[n,h,:] @ R[h] ----------------
__global__ __launch_bounds__(256) void rel_kernel(
    const float* __restrict__ X, const float* __restrict__ R,
    float* __restrict__ Y, int n)
{
    __shared__ float sR[NH * HD * HD];   // 8192 floats = 32KB
    __shared__ float sx[HIDC];
    int tid = threadIdx.x;
    for (int i = tid; i < NH * HD * HD; i += 256) sR[i] = R[i];
    __syncthreads();

    int h = tid >> 5, j = tid & 31;
    const float* Rh = &sR[h * HD * HD];
    int base = blockIdx.x * 16;

    for (int it = 0; it < 16; it++) {
        int node = base + it;
        if (node < n) sx[tid] = X[(size_t)node * HIDC + tid];
        __syncthreads();
        if (node < n) {
            const float* xh = &sx[h * HD];
            float acc = 0.f;
#pragma unroll
            for (int d = 0; d < HD; d++)
                acc += xh[d] * Rh[d * HD + j];
            Y[(size_t)node * HIDC + tid] = acc;
        }
        __syncthreads();
    }
}

// ---------------- edge kernels ----------------
__global__ __launch_bounds__(256) void edge_logits_kernel(
    const int* __restrict__ src, const int* __restrict__ dst,
    const float* __restrict__ krel, const float* __restrict__ Qt,
    const float* __restrict__ prel, float* __restrict__ logits,
    unsigned* __restrict__ amax, int E)
{
    int e = (blockIdx.x * 256 + threadIdx.x) >> 5;
    int lane = threadIdx.x & 31;
    if (e >= E) return;
    int s = src[e], d = dst[e];
    const float* kp = krel + (size_t)s * HIDC;
    const float* qp = Qt   + (size_t)d * HIDC;
    const float scale = 0.17677669529663687f;   // 1/sqrt(32)

#pragma unroll
    for (int h = 0; h < NH; h++) {
        float v = kp[h * HD + lane] * qp[h * HD + lane];
#pragma unroll
        for (int o = 16; o; o >>= 1) v += __shfl_down_sync(0xffffffffu, v, o);
        if (lane == 0) {
            float lg = v * prel[h] * scale;
            logits[(size_t)e * NH + h] = lg;
            atomicMax(&amax[(size_t)d * NH + h], f2u_ord(lg));
        }
    }
}

__global__ void edge_exp_kernel(
    const int* __restrict__ dst, float* __restrict__ logits,
    const unsigned* __restrict__ amax, float* __restrict__ den, int total)
{
    int i = blockIdx.x * blockDim.x + threadIdx.x;
    if (i >= total) return;
    int e = i >> 3, h = i & 7;
    int d = dst[e];
    float m  = u2f_ord(amax[(size_t)d * NH + h]);
    float ex = expf(logits[i] - m);
    logits[i] = ex;
    atomicAdd(&den[(size_t)d * NH + h], ex);
}

__global__ __launch_bounds__(256) void edge_msg_kernel(
    const int* __restrict__ src, const int* __restrict__ dst,
    const float* __restrict__ logits, const float* __restrict__ den,
    const float* __restrict__ vrel, float* __restrict__ outt, int E)
{
    int e = (blockIdx.x * 256 + threadIdx.x) >> 5;
    int lane = threadIdx.x & 31;
    if (e >= E) return;
    int s = src[e], d = dst[e];
#pragma unroll
    for (int h = 0; h < NH; h++) {
        float c = logits[(size_t)e * NH + h] / (den[(size_t)d * NH + h] + 1e-16f);
        atomicAdd(&outt[(size_t)d * HIDC + h * HD + lane],
                  vrel[(size_t)s * HIDC + h * HD + lane] * c);
    }
}

// ---------------- elementwise ----------------
__global__ void fill_kernel(float* p, float v, size_t n) {
    size_t i = (size_t)blockIdx.x * blockDim.x + threadIdx.x;
    size_t stride = (size_t)gridDim.x * blockDim.x;
    for (; i < n; i += stride) p[i] = v;
}

__global__ void gelu_kernel(const float* __restrict__ in, float* __restrict__ out, size_t n) {
    size_t i = (size_t)blockIdx.x * blockDim.x + threadIdx.x;
    size_t stride = (size_t)gridDim.x * blockDim.x;
    for (; i < n; i += stride) {
        float x = in[i];
        out[i] = 0.5f * x * (1.f + erff(x * 0.70710678118654752f));
    }
}

__global__ void skip_kernel(const float* __restrict__ o, const float* __restrict__ skipp,
                            float* __restrict__ xs, size_t n) {
    float s = *skipp;
    float g = 1.f / (1.f + expf(-s));
    size_t i = (size_t)blockIdx.x * blockDim.x + threadIdx.x;
    size_t stride = (size_t)gridDim.x * blockDim.x;
    for (; i < n; i += stride)
        xs[i] = g * o[i] + (1.f - g) * xs[i];
}

// ---------------- host orchestration ----------------
static void launch_gemm(const float* A, const float* B, const float* bias, float* C,
                        int M, int N, int K, int act) {
    dim3 grid(N / 64, (M + 127) / 128);
    sgemm_kernel<<<grid, 256>>>(A, B, bias, C, M, N, K, act);
}

static inline int ew_grid(size_t n) {
    size_t b = (n + 255) / 256;
    return (int)(b > 16384 ? 16384 : b);
}

extern "C" void kernel_launch(void* const* d_in, const int* in_sizes, int n_in,
                              void* d_out, int out_size)
{
    (void)in_sizes; (void)n_in; (void)out_size;

    const float* x_user   = (const float*)d_in[0];
    const float* x_movie  = (const float*)d_in[1];
    const float* x_review = (const float*)d_in[2];
    const int*  srcp[3] = {(const int*)d_in[3], (const int*)d_in[5], (const int*)d_in[7]};
    const int*  dstp[3] = {(const int*)d_in[4], (const int*)d_in[6], (const int*)d_in[8]};
    const float* W1 = (const float*)d_in[9];
    const float* b1 = (const float*)d_in[10];
    const float* W2 = (const float*)d_in[11];
    const float* b2 = (const float*)d_in[12];
    const float* Wk = (const float*)d_in[13];
    const float* bk = (const float*)d_in[14];
    const float* Wq = (const float*)d_in[15];
    const float* bq = (const float*)d_in[16];
    const float* Wv = (const float*)d_in[17];
    const float* bv = (const float*)d_in[18];
    const float* Wa = (const float*)d_in[19];
    const float* ba = (const float*)d_in[20];
    const float* skp   = (const float*)d_in[21];
    const float* a_rel = (const float*)d_in[22];
    const float* m_rel = (const float*)d_in[23];
    const float* p_rel = (const float*)d_in[24];

    float *xs, *Kb, *Qb, *Vb, *outb, *krel, *vrel, *logitsb, *denb;
    unsigned* amaxb;
    cudaGetSymbolAddress((void**)&xs,     g_xs);
    cudaGetSymbolAddress((void**)&Kb,     g_K);
    cudaGetSymbolAddress((void**)&Qb,     g_Q);
    cudaGetSymbolAddress((void**)&Vb,     g_V);
    cudaGetSymbolAddress((void**)&outb,   g_out);
    cudaGetSymbolAddress((void**)&krel,   g_krel);
    cudaGetSymbolAddress((void**)&vrel,   g_vrel);
    cudaGetSymbolAddress((void**)&logitsb,g_logits);
    cudaGetSymbolAddress((void**)&amaxb,  g_amax);
    cudaGetSymbolAddress((void**)&denb,   g_den);

    const int    cnt[3]  = {NU, NM, NRV};
    const size_t roff[3] = {0, (size_t)NU, (size_t)NU + NM};
    const int styp[3] = {1, 0, 2};
    const int dtyp[3] = {2, 2, 0};

    // ---- input MLP: xs[t] = lrelu(x_t @ W1 + b1) ----
    launch_gemm(x_user,   W1, b1, xs + roff[0] * HIDC, NU,  HIDC, 768, 1);
    launch_gemm(x_movie,  W1, b1, xs + roff[1] * HIDC, NM,  HIDC, 768, 1);
    launch_gemm(x_review, W1, b1, xs + roff[2] * HIDC, NRV, HIDC, 768, 1);

    for (int l = 0; l < 2; l++) {
        // K/Q/V projections per node type
        for (int t = 0; t < 3; t++) {
            size_t wofs = ((size_t)l * 3 + t) * HIDC * HIDC;
            size_t bofs = ((size_t)l * 3 + t) * HIDC;
            launch_gemm(xs + roff[t] * HIDC, Wk + wofs, bk + bofs, Kb + roff[t] * HIDC, cnt[t], HIDC, HIDC, 0);
            launch_gemm(xs + roff[t] * HIDC, Wq + wofs, bq + bofs, Qb + roff[t] * HIDC, cnt[t], HIDC, HIDC, 0);
            launch_gemm(xs + roff[t] * HIDC, Wv + wofs, bv + bofs, Vb + roff[t] * HIDC, cnt[t], HIDC, HIDC, 0);
        }

        // zero attention accumulators
        fill_kernel<<<ew_grid((size_t)NALL * HIDC), 256>>>(outb, 0.f, (size_t)NALL * HIDC);

        for (int e = 0; e < 3; e++) {
            int s = styp[e], t = dtyp[e];
            size_t rofs = ((size_t)l * 3 + e) * NH * HD * HD;

            rel_kernel<<<(cnt[s] + 15) / 16, 256>>>(Kb + roff[s] * HIDC, a_rel + rofs, krel, cnt[s]);
            rel_kernel<<<(cnt[s] + 15) / 16, 256>>>(Vb + roff[s] * HIDC, m_rel + rofs, vrel, cnt[s]);

            fill_kernel<<<ew_grid((size_t)cnt[t] * NH), 256>>>((float*)amaxb, 0.f, (size_t)cnt[t] * NH);
            fill_kernel<<<ew_grid((size_t)cnt[t] * NH), 256>>>(denb, 0.f, (size_t)cnt[t] * NH);

            int nwb = (NE + 7) / 8;   // 8 warps/block, 1 warp/edge
            edge_logits_kernel<<<nwb, 256>>>(srcp[e], dstp[e], krel, Qb + roff[t] * HIDC,
                                             p_rel + ((size_t)l * 3 + e) * NH,
                                             logitsb, amaxb, NE);
            edge_exp_kernel<<<(NE * NH + 255) / 256, 256>>>(dstp[e], logitsb, amaxb, denb, NE * NH);
            edge_msg_kernel<<<nwb, 256>>>(srcp[e], dstp[e], logitsb, denb, vrel,
                                          outb + roff[t] * HIDC, NE);
        }

        // per-type: xs = g * (gelu(out) @ Wa + ba) + (1-g) * xs
        gelu_kernel<<<ew_grid((size_t)NALL * HIDC), 256>>>(outb, Vb, (size_t)NALL * HIDC);
        for (int t = 0; t < 3; t++) {
            size_t wofs = ((size_t)l * 3 + t) * HIDC * HIDC;
            size_t bofs = ((size_t)l * 3 + t) * HIDC;
            launch_gemm(Vb + roff[t] * HIDC, Wa + wofs, ba + bofs, Kb + roff[t] * HIDC, cnt[t], HIDC, HIDC, 0);
            skip_kernel<<<ew_grid((size_t)cnt[t] * HIDC), 256>>>(Kb + roff[t] * HIDC,
                                                                 skp + l * 3 + t,
                                                                 xs + roff[t] * HIDC,
                                                                 (size_t)cnt[t] * HIDC);
        }
    }

    // ---- output MLP: lrelu(xs @ W2 + b2), contiguous user|movie|review ----
    launch_gemm(xs, W2, b2, (float*)d_out, NALL, 128, HIDC, 1);
}

// round 10
// speedup vs baseline: 1.9162x; 1.9162x over previous
#include <cuda_runtime.h>
#include <math.h>
#include <stdint.h>

// ---------------- problem constants ----------------
#define NU   50000
#define NM   20000
#define NRV  200000
#define NALL 270000
#define HIDC 256
#define NE   200000
#define NH   8
#define HD   32
#define LRS  0.01f   // leaky relu slope

// ---------------- device scratch (no allocations allowed) ----------------
__device__ float g_xs [(size_t)NALL * HIDC];
__device__ float g_K  [(size_t)NALL * HIDC];
__device__ float g_Q  [(size_t)NALL * HIDC];
__device__ float g_V  [(size_t)NALL * HIDC];
__device__ float g_out[(size_t)NALL * HIDC];
__device__ float g_krel[(size_t)NRV * HIDC];
__device__ float g_vrel[(size_t)NRV * HIDC];
__device__ float g_logits[(size_t)NE * NH];
__device__ unsigned g_amax[(size_t)NALL * NH];
__device__ float g_den [(size_t)NALL * NH];

// order-preserving float<->uint mapping for atomicMax on floats
__device__ __forceinline__ unsigned f2u_ord(float f) {
    unsigned u = __float_as_uint(f);
    return (u & 0x80000000u) ? ~u : (u | 0x80000000u);
}
__device__ __forceinline__ float u2f_ord(unsigned u) {
    return (u & 0x80000000u) ? __uint_as_float(u & 0x7fffffffu)
                             : __uint_as_float(~u);
}

__device__ __forceinline__ uint32_t f2tf32(float f) {
    uint32_t r;
    asm("cvt.rna.tf32.f32 %0, %1;" : "=r"(r) : "f"(f));
    return r;
}

// ================= TF32 tensor-core GEMM =================
// C[M,N] = act(A[M,K] * B[K,N] + bias)
// Block tile 128x128, BK=16, 256 threads (8 warps, warp tile 32x64),
// mma.sync.m16n8k8 tf32, cp.async double-buffered smem.
// Requires N % 128 == 0, K % 16 == 0 (true at all call sites). M guarded.

#define AST 20    // As row stride (floats): conflict-free fragment loads
#define BST 136   // Bs row stride (floats): 136 mod 32 = 8 -> 8t+g distinct

__device__ __forceinline__ void load_tiles(
    float (*Asb)[AST], float (*Bsb)[BST],
    const float* __restrict__ A, const float* __restrict__ B,
    int M, int N, int K, int m0, int n0, int k0, int tid)
{
    // A tile: 128 rows x 16 floats = 512 float4 -> 2 per thread
#pragma unroll
    for (int i = 0; i < 2; i++) {
        int f = tid + i * 256;
        int row = f >> 2, c4 = f & 3;
        uint32_t sm = (uint32_t)__cvta_generic_to_shared(&Asb[row][c4 * 4]);
        const float* gm = A + (size_t)(m0 + row) * K + k0 + c4 * 4;
        int v = (m0 + row < M) ? 16 : 0;
        asm volatile("cp.async.ca.shared.global [%0], [%1], 16, %2;\n"
                     :: "r"(sm), "l"(gm), "r"(v));
    }
    // B tile: 16 rows x 128 floats = 512 float4 -> 2 per thread
#pragma unroll
    for (int i = 0; i < 2; i++) {
        int f = tid + i * 256;
        int row = f >> 5, c4 = f & 31;
        uint32_t sm = (uint32_t)__cvta_generic_to_shared(&Bsb[row][c4 * 4]);
        const float* gm = B + (size_t)(k0 + row) * N + n0 + c4 * 4;
        asm volatile("cp.async.cg.shared.global [%0], [%1], 16;\n"
                     :: "r"(sm), "l"(gm));
    }
}

__global__ __launch_bounds__(256, 2) void tf32gemm_kernel(
    const float* __restrict__ A, const float* __restrict__ B,
    const float* __restrict__ bias, float* __restrict__ C,
    int M, int N, int K, int act)
{
    __shared__ __align__(16) float As[2][128][AST];  // 20480 B
    __shared__ __align__(16) float Bs[2][16][BST];   // 17408 B

    int tid  = threadIdx.x;
    int lane = tid & 31, warp = tid >> 5;
    int g = lane >> 2, t = lane & 3;        // mma groupID / threadInGroup
    int warpM = warp & 3, warpN = warp >> 2;
    int m0 = blockIdx.y * 128;
    int n0 = blockIdx.x * 128;

    float acc[2][8][4];
#pragma unroll
    for (int mt = 0; mt < 2; mt++)
#pragma unroll
        for (int nt = 0; nt < 8; nt++)
#pragma unroll
            for (int j = 0; j < 4; j++) acc[mt][nt][j] = 0.f;

    int nk = K >> 4;

    load_tiles(As[0], Bs[0], A, B, M, N, K, m0, n0, 0, tid);
    asm volatile("cp.async.commit_group;\n");

    for (int kt = 0; kt < nk; kt++) {
        int buf = kt & 1;
        if (kt + 1 < nk) {
            load_tiles(As[buf ^ 1], Bs[buf ^ 1], A, B, M, N, K, m0, n0,
                       (kt + 1) << 4, tid);
            asm volatile("cp.async.commit_group;\n");
            asm volatile("cp.async.wait_group 1;\n");
        } else {
            asm volatile("cp.async.wait_group 0;\n");
        }
        __syncthreads();

#pragma unroll
        for (int ks = 0; ks < 2; ks++) {
            int k0 = ks * 8;
            uint32_t af[2][4];
#pragma unroll
            for (int mt = 0; mt < 2; mt++) {
                int r = warpM * 32 + mt * 16 + g;
                af[mt][0] = f2tf32(As[buf][r][k0 + t]);
                af[mt][1] = f2tf32(As[buf][r + 8][k0 + t]);
                af[mt][2] = f2tf32(As[buf][r][k0 + t + 4]);
                af[mt][3] = f2tf32(As[buf][r + 8][k0 + t + 4]);
            }
            uint32_t bf[8][2];
#pragma unroll
            for (int nt = 0; nt < 8; nt++) {
                int c = warpN * 64 + nt * 8 + g;
                bf[nt][0] = f2tf32(Bs[buf][k0 + t][c]);
                bf[nt][1] = f2tf32(Bs[buf][k0 + t + 4][c]);
            }
#pragma unroll
            for (int mt = 0; mt < 2; mt++)
#pragma unroll
                for (int nt = 0; nt < 8; nt++)
                    asm volatile(
                        "mma.sync.aligned.m16n8k8.row.col.f32.tf32.tf32.f32 "
                        "{%0,%1,%2,%3}, {%4,%5,%6,%7}, {%8,%9}, {%0,%1,%2,%3};\n"
                        : "+f"(acc[mt][nt][0]), "+f"(acc[mt][nt][1]),
                          "+f"(acc[mt][nt][2]), "+f"(acc[mt][nt][3])
                        : "r"(af[mt][0]), "r"(af[mt][1]),
                          "r"(af[mt][2]), "r"(af[mt][3]),
                          "r"(bf[nt][0]), "r"(bf[nt][1]));
        }
        __syncthreads();
    }

    // ---- epilogue: bias + activation + store ----
#pragma unroll
    for (int mt = 0; mt < 2; mt++) {
        int r0 = m0 + warpM * 32 + mt * 16 + g;
        int r1 = r0 + 8;
#pragma unroll
        for (int nt = 0; nt < 8; nt++) {
            int col = n0 + warpN * 64 + nt * 8 + t * 2;
            float bv0 = bias[col], bv1 = bias[col + 1];
            float v0 = acc[mt][nt][0] + bv0;
            float v1 = acc[mt][nt][1] + bv1;
            float v2 = acc[mt][nt][2] + bv0;
            float v3 = acc[mt][nt][3] + bv1;
            if (act == 1) {
                v0 = (v0 > 0.f) ? v0 : LRS * v0;
                v1 = (v1 > 0.f) ? v1 : LRS * v1;
                v2 = (v2 > 0.f) ? v2 : LRS * v2;
                v3 = (v3 > 0.f) ? v3 : LRS * v3;
            }
            if (r0 < M) *(float2*)(C + (size_t)r0 * N + col) = make_float2(v0, v1);
            if (r1 < M) *(float2*)(C + (size_t)r1 * N + col) = make_float2(v2, v3);
        }
    }
}

// ---------------- per-head relation transform: Y[n,h,:] = X[n,h,:] @ R[h] ----------------
__global__ __launch_bounds__(256) void rel_kernel(
    const float* __restrict__ X, const float* __restrict__ R,
    float* __restrict__ Y, int n)
{
    __shared__ float sR[NH * HD * HD];   // 8192 floats = 32KB
    __shared__ float sx[HIDC];
    int tid = threadIdx.x;
    for (int i = tid; i < NH * HD * HD; i += 256) sR[i] = R[i];
    __syncthreads();

    int h = tid >> 5, j = tid & 31;
    const float* Rh = &sR[h * HD * HD];
    int base = blockIdx.x * 16;

    for (int it = 0; it < 16; it++) {
        int node = base + it;
        if (node < n) sx[tid] = X[(size_t)node * HIDC + tid];
        __syncthreads();
        if (node < n) {
            const float* xh = &sx[h * HD];
            float acc = 0.f;
#pragma unroll
            for (int d = 0; d < HD; d++)
                acc += xh[d] * Rh[d * HD + j];
            Y[(size_t)node * HIDC + tid] = acc;
        }
        __syncthreads();
    }
}

// ---------------- edge kernels ----------------
__global__ __launch_bounds__(256) void edge_logits_kernel(
    const int* __restrict__ src, const int* __restrict__ dst,
    const float* __restrict__ krel, const float* __restrict__ Qt,
    const float* __restrict__ prel, float* __restrict__ logits,
    unsigned* __restrict__ amax, int E)
{
    int e = (blockIdx.x * 256 + threadIdx.x) >> 5;
    int lane = threadIdx.x & 31;
    if (e >= E) return;
    int s = src[e], d = dst[e];
    const float* kp = krel + (size_t)s * HIDC;
    const float* qp = Qt   + (size_t)d * HIDC;
    const float scale = 0.17677669529663687f;   // 1/sqrt(32)

#pragma unroll
    for (int h = 0; h < NH; h++) {
        float v = kp[h * HD + lane] * qp[h * HD + lane];
#pragma unroll
        for (int o = 16; o; o >>= 1) v += __shfl_down_sync(0xffffffffu, v, o);
        if (lane == 0) {
            float lg = v * prel[h] * scale;
            logits[(size_t)e * NH + h] = lg;
            atomicMax(&amax[(size_t)d * NH + h], f2u_ord(lg));
        }
    }
}

__global__ void edge_exp_kernel(
    const int* __restrict__ dst, float* __restrict__ logits,
    const unsigned* __restrict__ amax, float* __restrict__ den, int total)
{
    int i = blockIdx.x * blockDim.x + threadIdx.x;
    if (i >= total) return;
    int e = i >> 3, h = i & 7;
    int d = dst[e];
    float m  = u2f_ord(amax[(size_t)d * NH + h]);
    float ex = expf(logits[i] - m);
    logits[i] = ex;
    atomicAdd(&den[(size_t)d * NH + h], ex);
}

__global__ __launch_bounds__(256) void edge_msg_kernel(
    const int* __restrict__ src, const int* __restrict__ dst,
    const float* __restrict__ logits, const float* __restrict__ den,
    const float* __restrict__ vrel, float* __restrict__ outt, int E)
{
    int e = (blockIdx.x * 256 + threadIdx.x) >> 5;
    int lane = threadIdx.x & 31;
    if (e >= E) return;
    int s = src[e], d = dst[e];
#pragma unroll
    for (int h = 0; h < NH; h++) {
        float c = logits[(size_t)e * NH + h] / (den[(size_t)d * NH + h] + 1e-16f);
        atomicAdd(&outt[(size_t)d * HIDC + h * HD + lane],
                  vrel[(size_t)s * HIDC + h * HD + lane] * c);
    }
}

// ---------------- elementwise ----------------
__global__ void fill_kernel(float* p, float v, size_t n) {
    size_t i = (size_t)blockIdx.x * blockDim.x + threadIdx.x;
    size_t stride = (size_t)gridDim.x * blockDim.x;
    for (; i < n; i += stride) p[i] = v;
}

__global__ void gelu_kernel(const float* __restrict__ in, float* __restrict__ out, size_t n) {
    size_t i = (size_t)blockIdx.x * blockDim.x + threadIdx.x;
    size_t stride = (size_t)gridDim.x * blockDim.x;
    for (; i < n; i += stride) {
        float x = in[i];
        out[i] = 0.5f * x * (1.f + erff(x * 0.70710678118654752f));
    }
}

__global__ void skip_kernel(const float* __restrict__ o, const float* __restrict__ skipp,
                            float* __restrict__ xs, size_t n) {
    float s = *skipp;
    float g = 1.f / (1.f + expf(-s));
    size_t i = (size_t)blockIdx.x * blockDim.x + threadIdx.x;
    size_t stride = (size_t)gridDim.x * blockDim.x;
    for (; i < n; i += stride)
        xs[i] = g * o[i] + (1.f - g) * xs[i];
}

// ---------------- host orchestration ----------------
static void launch_gemm(const float* A, const float* B, const float* bias, float* C,
                        int M, int N, int K, int act) {
    dim3 grid(N / 128, (M + 127) / 128);
    tf32gemm_kernel<<<grid, 256>>>(A, B, bias, C, M, N, K, act);
}

static inline int ew_grid(size_t n) {
    size_t b = (n + 255) / 256;
    return (int)(b > 16384 ? 16384 : b);
}

extern "C" void kernel_launch(void* const* d_in, const int* in_sizes, int n_in,
                              void* d_out, int out_size)
{
    (void)in_sizes; (void)n_in; (void)out_size;

    const float* x_user   = (const float*)d_in[0];
    const float* x_movie  = (const float*)d_in[1];
    const float* x_review = (const float*)d_in[2];
    const int*  srcp[3] = {(const int*)d_in[3], (const int*)d_in[5], (const int*)d_in[7]};
    const int*  dstp[3] = {(const int*)d_in[4], (const int*)d_in[6], (const int*)d_in[8]};
    const float* W1 = (const float*)d_in[9];
    const float* b1 = (const float*)d_in[10];
    const float* W2 = (const float*)d_in[11];
    const float* b2 = (const float*)d_in[12];
    const float* Wk = (const float*)d_in[13];
    const float* bk = (const float*)d_in[14];
    const float* Wq = (const float*)d_in[15];
    const float* bq = (const float*)d_in[16];
    const float* Wv = (const float*)d_in[17];
    const float* bv = (const float*)d_in[18];
    const float* Wa = (const float*)d_in[19];
    const float* ba = (const float*)d_in[20];
    const float* skp   = (const float*)d_in[21];
    const float* a_rel = (const float*)d_in[22];
    const float* m_rel = (const float*)d_in[23];
    const float* p_rel = (const float*)d_in[24];

    float *xs, *Kb, *Qb, *Vb, *outb, *krel, *vrel, *logitsb, *denb;
    unsigned* amaxb;
    cudaGetSymbolAddress((void**)&xs,     g_xs);
    cudaGetSymbolAddress((void**)&Kb,     g_K);
    cudaGetSymbolAddress((void**)&Qb,     g_Q);
    cudaGetSymbolAddress((void**)&Vb,     g_V);
    cudaGetSymbolAddress((void**)&outb,   g_out);
    cudaGetSymbolAddress((void**)&krel,   g_krel);
    cudaGetSymbolAddress((void**)&vrel,   g_vrel);
    cudaGetSymbolAddress((void**)&logitsb,g_logits);
    cudaGetSymbolAddress((void**)&amaxb,  g_amax);
    cudaGetSymbolAddress((void**)&denb,   g_den);

    const int    cnt[3]  = {NU, NM, NRV};
    const size_t roff[3] = {0, (size_t)NU, (size_t)NU + NM};
    const int styp[3] = {1, 0, 2};
    const int dtyp[3] = {2, 2, 0};

    // ---- input MLP: xs[t] = lrelu(x_t @ W1 + b1) ----
    launch_gemm(x_user,   W1, b1, xs + roff[0] * HIDC, NU,  HIDC, 768, 1);
    launch_gemm(x_movie,  W1, b1, xs + roff[1] * HIDC, NM,  HIDC, 768, 1);
    launch_gemm(x_review, W1, b1, xs + roff[2] * HIDC, NRV, HIDC, 768, 1);

    for (int l = 0; l < 2; l++) {
        // K/Q/V projections per node type
        for (int t = 0; t < 3; t++) {
            size_t wofs = ((size_t)l * 3 + t) * HIDC * HIDC;
            size_t bofs = ((size_t)l * 3 + t) * HIDC;
            launch_gemm(xs + roff[t] * HIDC, Wk + wofs, bk + bofs, Kb + roff[t] * HIDC, cnt[t], HIDC, HIDC, 0);
            launch_gemm(xs + roff[t] * HIDC, Wq + wofs, bq + bofs, Qb + roff[t] * HIDC, cnt[t], HIDC, HIDC, 0);
            launch_gemm(xs + roff[t] * HIDC, Wv + wofs, bv + bofs, Vb + roff[t] * HIDC, cnt[t], HIDC, HIDC, 0);
        }

        // zero attention accumulators
        fill_kernel<<<ew_grid((size_t)NALL * HIDC), 256>>>(outb, 0.f, (size_t)NALL * HIDC);

        for (int e = 0; e < 3; e++) {
            int s = styp[e], t = dtyp[e];
            size_t rofs = ((size_t)l * 3 + e) * NH * HD * HD;

            rel_kernel<<<(cnt[s] + 15) / 16, 256>>>(Kb + roff[s] * HIDC, a_rel + rofs, krel, cnt[s]);
            rel_kernel<<<(cnt[s] + 15) / 16, 256>>>(Vb + roff[s] * HIDC, m_rel + rofs, vrel, cnt[s]);

            fill_kernel<<<ew_grid((size_t)cnt[t] * NH), 256>>>((float*)amaxb, 0.f, (size_t)cnt[t] * NH);
            fill_kernel<<<ew_grid((size_t)cnt[t] * NH), 256>>>(denb, 0.f, (size_t)cnt[t] * NH);

            int nwb = (NE + 7) / 8;   // 8 warps/block, 1 warp/edge
            edge_logits_kernel<<<nwb, 256>>>(srcp[e], dstp[e], krel, Qb + roff[t] * HIDC,
                                             p_rel + ((size_t)l * 3 + e) * NH,
                                             logitsb, amaxb, NE);
            edge_exp_kernel<<<(NE * NH + 255) / 256, 256>>>(dstp[e], logitsb, amaxb, denb, NE * NH);
            edge_msg_kernel<<<nwb, 256>>>(srcp[e], dstp[e], logitsb, denb, vrel,
                                          outb + roff[t] * HIDC, NE);
        }

        // per-type: xs = g * (gelu(out) @ Wa + ba) + (1-g) * xs
        gelu_kernel<<<ew_grid((size_t)NALL * HIDC), 256>>>(outb, Vb, (size_t)NALL * HIDC);
        for (int t = 0; t < 3; t++) {
            size_t wofs = ((size_t)l * 3 + t) * HIDC * HIDC;
            size_t bofs = ((size_t)l * 3 + t) * HIDC;
            launch_gemm(Vb + roff[t] * HIDC, Wa + wofs, ba + bofs, Kb + roff[t] * HIDC, cnt[t], HIDC, HIDC, 0);
            skip_kernel<<<ew_grid((size_t)cnt[t] * HIDC), 256>>>(Kb + roff[t] * HIDC,
                                                                 skp + l * 3 + t,
                                                                 xs + roff[t] * HIDC,
                                                                 (size_t)cnt[t] * HIDC);
        }
    }

    // ---- output MLP: lrelu(xs @ W2 + b2), contiguous user|movie|review ----
    launch_gemm(xs, W2, b2, (float*)d_out, NALL, 128, HIDC, 1);
}

// round 11
// speedup vs baseline: 2.5534x; 1.3326x over previous
#include <cuda_runtime.h>
#include <math.h>
#include <stdint.h>

// ---------------- problem constants ----------------
#define NU   50000
#define NM   20000
#define NRV  200000
#define NALL 270000
#define HIDC 256
#define NE   200000
#define NH   8
#define HD   32
#define LRS  0.01f   // leaky relu slope

// ---------------- device scratch (no allocations allowed) ----------------
__device__ float g_xs [(size_t)NALL * HIDC];
__device__ float g_Q  [(size_t)NALL * HIDC];
__device__ float g_gelu[(size_t)NALL * HIDC];
__device__ float g_out[(size_t)NALL * HIDC];
__device__ float g_krel[(size_t)NRV * HIDC];
__device__ float g_vrel[(size_t)NRV * HIDC];
__device__ float g_logits[(size_t)NE * NH];
__device__ unsigned g_amax[(size_t)NALL * NH];
__device__ float g_den [(size_t)NALL * NH];
// combined relation-folded weights: [12][256*256], biases [12][256]
// slot c = l*3+e for K-path (0..5), 6 + l*3+e for V-path (6..11)
__device__ float g_wc[12 * HIDC * HIDC];
__device__ float g_bc[12 * HIDC];

// order-preserving float<->uint mapping for atomicMax on floats
__device__ __forceinline__ unsigned f2u_ord(float f) {
    unsigned u = __float_as_uint(f);
    return (u & 0x80000000u) ? ~u : (u | 0x80000000u);
}
__device__ __forceinline__ float u2f_ord(unsigned u) {
    return (u & 0x80000000u) ? __uint_as_float(u & 0x7fffffffu)
                             : __uint_as_float(~u);
}

__device__ __forceinline__ uint32_t f2tf32(float f) {
    uint32_t r;
    asm("cvt.rna.tf32.f32 %0, %1;" : "=r"(r) : "f"(f));
    return r;
}

// ---------------- weight fold: WC = Wsrc @ blockdiag(Arel), bC = bsrc @ BD(Arel) ----------------
// Arel: [8][32][32]. WC[i, h*32+j] = sum_d Wsrc[i, h*32+d] * Arel[h][d][j]
// grid.x = 8 (32 rows each), 256 threads (thread = output column).
__global__ __launch_bounds__(256) void wcomb_kernel(
    const float* __restrict__ Wsrc, const float* __restrict__ bsrc,
    const float* __restrict__ Arel,
    float* __restrict__ WC, float* __restrict__ bC)
{
    __shared__ float sA[NH * HD * HD];   // 32KB
    int tid = threadIdx.x;
    for (int i = tid; i < NH * HD * HD; i += 256) sA[i] = Arel[i];
    __syncthreads();

    int h = tid >> 5, j = tid & 31;
    const float* Ah = &sA[h * HD * HD];
    int r0 = blockIdx.x * 32;
    for (int i = r0; i < r0 + 32; i++) {
        const float* wrow = Wsrc + (size_t)i * HIDC + h * HD;
        float acc = 0.f;
#pragma unroll
        for (int d = 0; d < HD; d++)
            acc += wrow[d] * Ah[d * HD + j];
        WC[(size_t)i * HIDC + tid] = acc;
    }
    if (blockIdx.x == 0) {
        const float* brow = bsrc + h * HD;
        float acc = 0.f;
#pragma unroll
        for (int d = 0; d < HD; d++)
            acc += brow[d] * Ah[d * HD + j];
        bC[tid] = acc;
    }
}

// ================= TF32 tensor-core GEMM =================
// C[M,N] = epilogue(A[M,K] * B[K,N] + bias)
// act: 0 = none, 1 = leaky relu, 2 = skip-blend (C = g*v + (1-g)*xold, g = sigmoid(*skipp))
// Block tile 128x128, BK=16, 256 threads (8 warps, warp tile 32x64),
// mma.sync.m16n8k8 tf32, cp.async double-buffered smem.
// Requires N % 128 == 0, K % 16 == 0 (true at all call sites). M guarded.

#define AST 20    // As row stride (floats): conflict-free fragment loads
#define BST 136   // Bs row stride (floats): 136 mod 32 = 8 -> 8t+g distinct

__device__ __forceinline__ void load_tiles(
    float (*Asb)[AST], float (*Bsb)[BST],
    const float* __restrict__ A, const float* __restrict__ B,
    int M, int N, int K, int m0, int n0, int k0, int tid)
{
    // A tile: 128 rows x 16 floats = 512 float4 -> 2 per thread
#pragma unroll
    for (int i = 0; i < 2; i++) {
        int f = tid + i * 256;
        int row = f >> 2, c4 = f & 3;
        uint32_t sm = (uint32_t)__cvta_generic_to_shared(&Asb[row][c4 * 4]);
        const float* gm = A + (size_t)(m0 + row) * K + k0 + c4 * 4;
        int v = (m0 + row < M) ? 16 : 0;
        asm volatile("cp.async.ca.shared.global [%0], [%1], 16, %2;\n"
                     :: "r"(sm), "l"(gm), "r"(v));
    }
    // B tile: 16 rows x 128 floats = 512 float4 -> 2 per thread
#pragma unroll
    for (int i = 0; i < 2; i++) {
        int f = tid + i * 256;
        int row = f >> 5, c4 = f & 31;
        uint32_t sm = (uint32_t)__cvta_generic_to_shared(&Bsb[row][c4 * 4]);
        const float* gm = B + (size_t)(k0 + row) * N + n0 + c4 * 4;
        asm volatile("cp.async.cg.shared.global [%0], [%1], 16;\n"
                     :: "r"(sm), "l"(gm));
    }
}

__global__ __launch_bounds__(256, 2) void tf32gemm_kernel(
    const float* __restrict__ A, const float* __restrict__ B,
    const float* __restrict__ bias, float* __restrict__ C,
    int M, int N, int K, int act,
    const float* __restrict__ skipp, const float* __restrict__ xold)
{
    __shared__ __align__(16) float As[2][128][AST];  // 20480 B
    __shared__ __align__(16) float Bs[2][16][BST];   // 17408 B

    int tid  = threadIdx.x;
    int lane = tid & 31, warp = tid >> 5;
    int g = lane >> 2, t = lane & 3;        // mma groupID / threadInGroup
    int warpM = warp & 3, warpN = warp >> 2;
    int m0 = blockIdx.y * 128;
    int n0 = blockIdx.x * 128;

    float acc[2][8][4];
#pragma unroll
    for (int mt = 0; mt < 2; mt++)
#pragma unroll
        for (int nt = 0; nt < 8; nt++)
#pragma unroll
            for (int j = 0; j < 4; j++) acc[mt][nt][j] = 0.f;

    int nk = K >> 4;

    load_tiles(As[0], Bs[0], A, B, M, N, K, m0, n0, 0, tid);
    asm volatile("cp.async.commit_group;\n");

    for (int kt = 0; kt < nk; kt++) {
        int buf = kt & 1;
        if (kt + 1 < nk) {
            load_tiles(As[buf ^ 1], Bs[buf ^ 1], A, B, M, N, K, m0, n0,
                       (kt + 1) << 4, tid);
            asm volatile("cp.async.commit_group;\n");
            asm volatile("cp.async.wait_group 1;\n");
        } else {
            asm volatile("cp.async.wait_group 0;\n");
        }
        __syncthreads();

#pragma unroll
        for (int ks = 0; ks < 2; ks++) {
            int k0 = ks * 8;
            uint32_t af[2][4];
#pragma unroll
            for (int mt = 0; mt < 2; mt++) {
                int r = warpM * 32 + mt * 16 + g;
                af[mt][0] = f2tf32(As[buf][r][k0 + t]);
                af[mt][1] = f2tf32(As[buf][r + 8][k0 + t]);
                af[mt][2] = f2tf32(As[buf][r][k0 + t + 4]);
                af[mt][3] = f2tf32(As[buf][r + 8][k0 + t + 4]);
            }
            uint32_t bf[8][2];
#pragma unroll
            for (int nt = 0; nt < 8; nt++) {
                int c = warpN * 64 + nt * 8 + g;
                bf[nt][0] = f2tf32(Bs[buf][k0 + t][c]);
                bf[nt][1] = f2tf32(Bs[buf][k0 + t + 4][c]);
            }
#pragma unroll
            for (int mt = 0; mt < 2; mt++)
#pragma unroll
                for (int nt = 0; nt < 8; nt++)
                    asm volatile(
                        "mma.sync.aligned.m16n8k8.row.col.f32.tf32.tf32.f32 "
                        "{%0,%1,%2,%3}, {%4,%5,%6,%7}, {%8,%9}, {%0,%1,%2,%3};\n"
                        : "+f"(acc[mt][nt][0]), "+f"(acc[mt][nt][1]),
                          "+f"(acc[mt][nt][2]), "+f"(acc[mt][nt][3])
                        : "r"(af[mt][0]), "r"(af[mt][1]),
                          "r"(af[mt][2]), "r"(af[mt][3]),
                          "r"(bf[nt][0]), "r"(bf[nt][1]));
        }
        __syncthreads();
    }

    // ---- epilogue: bias + activation / skip-blend + store ----
    float gk = 0.f;
    if (act == 2) {
        float s = *skipp;
        gk = 1.f / (1.f + expf(-s));
    }
#pragma unroll
    for (int mt = 0; mt < 2; mt++) {
        int r0 = m0 + warpM * 32 + mt * 16 + g;
        int r1 = r0 + 8;
#pragma unroll
        for (int nt = 0; nt < 8; nt++) {
            int col = n0 + warpN * 64 + nt * 8 + t * 2;
            float bv0 = bias[col], bv1 = bias[col + 1];
            float v0 = acc[mt][nt][0] + bv0;
            float v1 = acc[mt][nt][1] + bv1;
            float v2 = acc[mt][nt][2] + bv0;
            float v3 = acc[mt][nt][3] + bv1;
            if (act == 1) {
                v0 = (v0 > 0.f) ? v0 : LRS * v0;
                v1 = (v1 > 0.f) ? v1 : LRS * v1;
                v2 = (v2 > 0.f) ? v2 : LRS * v2;
                v3 = (v3 > 0.f) ? v3 : LRS * v3;
            } else if (act == 2) {
                if (r0 < M) {
                    float2 o = *(const float2*)(xold + (size_t)r0 * N + col);
                    v0 = gk * v0 + (1.f - gk) * o.x;
                    v1 = gk * v1 + (1.f - gk) * o.y;
                }
                if (r1 < M) {
                    float2 o = *(const float2*)(xold + (size_t)r1 * N + col);
                    v2 = gk * v2 + (1.f - gk) * o.x;
                    v3 = gk * v3 + (1.f - gk) * o.y;
                }
            }
            if (r0 < M) *(float2*)(C + (size_t)r0 * N + col) = make_float2(v0, v1);
            if (r1 < M) *(float2*)(C + (size_t)r1 * N + col) = make_float2(v2, v3);
        }
    }
}

// ---------------- edge kernels ----------------
__global__ __launch_bounds__(256) void edge_logits_kernel(
    const int* __restrict__ src, const int* __restrict__ dst,
    const float* __restrict__ krel, const float* __restrict__ Qt,
    const float* __restrict__ prel, float* __restrict__ logits,
    unsigned* __restrict__ amax, int E)
{
    int e = (blockIdx.x * 256 + threadIdx.x) >> 5;
    int lane = threadIdx.x & 31;
    if (e >= E) return;
    int s = src[e], d = dst[e];
    const float* kp = krel + (size_t)s * HIDC;
    const float* qp = Qt   + (size_t)d * HIDC;
    const float scale = 0.17677669529663687f;   // 1/sqrt(32)

#pragma unroll
    for (int h = 0; h < NH; h++) {
        float v = kp[h * HD + lane] * qp[h * HD + lane];
#pragma unroll
        for (int o = 16; o; o >>= 1) v += __shfl_down_sync(0xffffffffu, v, o);
        if (lane == 0) {
            float lg = v * prel[h] * scale;
            logits[(size_t)e * NH + h] = lg;
            atomicMax(&amax[(size_t)d * NH + h], f2u_ord(lg));
        }
    }
}

__global__ void edge_exp_kernel(
    const int* __restrict__ dst, float* __restrict__ logits,
    const unsigned* __restrict__ amax, float* __restrict__ den, int total)
{
    int i = blockIdx.x * blockDim.x + threadIdx.x;
    if (i >= total) return;
    int e = i >> 3, h = i & 7;
    int d = dst[e];
    float m  = u2f_ord(amax[(size_t)d * NH + h]);
    float ex = expf(logits[i] - m);
    logits[i] = ex;
    atomicAdd(&den[(size_t)d * NH + h], ex);
}

__global__ __launch_bounds__(256) void edge_msg_kernel(
    const int* __restrict__ src, const int* __restrict__ dst,
    const float* __restrict__ logits, const float* __restrict__ den,
    const float* __restrict__ vrel, float* __restrict__ outt, int E)
{
    int e = (blockIdx.x * 256 + threadIdx.x) >> 5;
    int lane = threadIdx.x & 31;
    if (e >= E) return;
    int s = src[e], d = dst[e];
#pragma unroll
    for (int h = 0; h < NH; h++) {
        float c = logits[(size_t)e * NH + h] / (den[(size_t)d * NH + h] + 1e-16f);
        atomicAdd(&outt[(size_t)d * HIDC + h * HD + lane],
                  vrel[(size_t)s * HIDC + h * HD + lane] * c);
    }
}

// ---------------- elementwise ----------------
__global__ void fill_kernel(float* p, float v, size_t n) {
    size_t i = (size_t)blockIdx.x * blockDim.x + threadIdx.x;
    size_t stride = (size_t)gridDim.x * blockDim.x;
    for (; i < n; i += stride) p[i] = v;
}

__global__ void gelu_kernel(const float* __restrict__ in, float* __restrict__ out, size_t n) {
    size_t i = (size_t)blockIdx.x * blockDim.x + threadIdx.x;
    size_t stride = (size_t)gridDim.x * blockDim.x;
    for (; i < n; i += stride) {
        float x = in[i];
        out[i] = 0.5f * x * (1.f + erff(x * 0.70710678118654752f));
    }
}

// ---------------- host orchestration ----------------
static void launch_gemm(const float* A, const float* B, const float* bias, float* C,
                        int M, int N, int K, int act) {
    dim3 grid(N / 128, (M + 127) / 128);
    tf32gemm_kernel<<<grid, 256>>>(A, B, bias, C, M, N, K, act, nullptr, nullptr);
}

static void launch_gemm_skip(const float* A, const float* B, const float* bias, float* C,
                             int M, int N, int K, const float* skipp, const float* xold) {
    dim3 grid(N / 128, (M + 127) / 128);
    tf32gemm_kernel<<<grid, 256>>>(A, B, bias, C, M, N, K, 2, skipp, xold);
}

static inline int ew_grid(size_t n) {
    size_t b = (n + 255) / 256;
    return (int)(b > 16384 ? 16384 : b);
}

extern "C" void kernel_launch(void* const* d_in, const int* in_sizes, int n_in,
                              void* d_out, int out_size)
{
    (void)in_sizes; (void)n_in; (void)out_size;

    const float* x_user   = (const float*)d_in[0];
    const float* x_movie  = (const float*)d_in[1];
    const float* x_review = (const float*)d_in[2];
    const int*  srcp[3] = {(const int*)d_in[3], (const int*)d_in[5], (const int*)d_in[7]};
    const int*  dstp[3] = {(const int*)d_in[4], (const int*)d_in[6], (const int*)d_in[8]};
    const float* W1 = (const float*)d_in[9];
    const float* b1 = (const float*)d_in[10];
    const float* W2 = (const float*)d_in[11];
    const float* b2 = (const float*)d_in[12];
    const float* Wk = (const float*)d_in[13];
    const float* bk = (const float*)d_in[14];
    const float* Wq = (const float*)d_in[15];
    const float* bq = (const float*)d_in[16];
    const float* Wv = (const float*)d_in[17];
    const float* bv = (const float*)d_in[18];
    const float* Wa = (const float*)d_in[19];
    const float* ba = (const float*)d_in[20];
    const float* skp   = (const float*)d_in[21];
    const float* a_rel = (const float*)d_in[22];
    const float* m_rel = (const float*)d_in[23];
    const float* p_rel = (const float*)d_in[24];

    float *xs, *Qb, *gelub, *outb, *krel, *vrel, *logitsb, *denb, *wc, *bc;
    unsigned* amaxb;
    cudaGetSymbolAddress((void**)&xs,     g_xs);
    cudaGetSymbolAddress((void**)&Qb,     g_Q);
    cudaGetSymbolAddress((void**)&gelub,  g_gelu);
    cudaGetSymbolAddress((void**)&outb,   g_out);
    cudaGetSymbolAddress((void**)&krel,   g_krel);
    cudaGetSymbolAddress((void**)&vrel,   g_vrel);
    cudaGetSymbolAddress((void**)&logitsb,g_logits);
    cudaGetSymbolAddress((void**)&amaxb,  g_amax);
    cudaGetSymbolAddress((void**)&denb,   g_den);
    cudaGetSymbolAddress((void**)&wc,     g_wc);
    cudaGetSymbolAddress((void**)&bc,     g_bc);

    const int    cnt[3]  = {NU, NM, NRV};
    const size_t roff[3] = {0, (size_t)NU, (size_t)NU + NM};
    const int styp[3] = {1, 0, 2};
    const int dtyp[3] = {2, 2, 0};

    // ---- fold relation matrices into K/V weights (fp32, once) ----
    for (int l = 0; l < 2; l++)
        for (int e = 0; e < 3; e++) {
            int s = styp[e];
            size_t wofs = ((size_t)l * 3 + s) * HIDC * HIDC;
            size_t bofs = ((size_t)l * 3 + s) * HIDC;
            size_t aofs = ((size_t)l * 3 + e) * NH * HD * HD;
            int cK = l * 3 + e, cV = 6 + l * 3 + e;
            wcomb_kernel<<<8, 256>>>(Wk + wofs, bk + bofs, a_rel + aofs,
                                     wc + (size_t)cK * HIDC * HIDC, bc + (size_t)cK * HIDC);
            wcomb_kernel<<<8, 256>>>(Wv + wofs, bv + bofs, m_rel + aofs,
                                     wc + (size_t)cV * HIDC * HIDC, bc + (size_t)cV * HIDC);
        }

    // ---- input MLP: xs[t] = lrelu(x_t @ W1 + b1) ----
    launch_gemm(x_user,   W1, b1, xs + roff[0] * HIDC, NU,  HIDC, 768, 1);
    launch_gemm(x_movie,  W1, b1, xs + roff[1] * HIDC, NM,  HIDC, 768, 1);
    launch_gemm(x_review, W1, b1, xs + roff[2] * HIDC, NRV, HIDC, 768, 1);

    for (int l = 0; l < 2; l++) {
        // Q projections (only dst types 0 and 2 are ever destinations)
        for (int ti = 0; ti < 2; ti++) {
            int t = (ti == 0) ? 0 : 2;
            size_t wofs = ((size_t)l * 3 + t) * HIDC * HIDC;
            size_t bofs = ((size_t)l * 3 + t) * HIDC;
            launch_gemm(xs + roff[t] * HIDC, Wq + wofs, bq + bofs, Qb + roff[t] * HIDC,
                        cnt[t], HIDC, HIDC, 0);
        }

        // zero attention accumulators
        fill_kernel<<<ew_grid((size_t)NALL * HIDC), 256>>>(outb, 0.f, (size_t)NALL * HIDC);

        for (int e = 0; e < 3; e++) {
            int s = styp[e], t = dtyp[e];
            int cK = l * 3 + e, cV = 6 + l * 3 + e;

            // relation-folded K and V projections (straight into krel/vrel)
            launch_gemm(xs + roff[s] * HIDC, wc + (size_t)cK * HIDC * HIDC,
                        bc + (size_t)cK * HIDC, krel, cnt[s], HIDC, HIDC, 0);
            launch_gemm(xs + roff[s] * HIDC, wc + (size_t)cV * HIDC * HIDC,
                        bc + (size_t)cV * HIDC, vrel, cnt[s], HIDC, HIDC, 0);

            fill_kernel<<<ew_grid((size_t)cnt[t] * NH), 256>>>((float*)amaxb, 0.f, (size_t)cnt[t] * NH);
            fill_kernel<<<ew_grid((size_t)cnt[t] * NH), 256>>>(denb, 0.f, (size_t)cnt[t] * NH);

            int nwb = (NE + 7) / 8;   // 8 warps/block, 1 warp/edge
            edge_logits_kernel<<<nwb, 256>>>(srcp[e], dstp[e], krel, Qb + roff[t] * HIDC,
                                             p_rel + ((size_t)l * 3 + e) * NH,
                                             logitsb, amaxb, NE);
            edge_exp_kernel<<<(NE * NH + 255) / 256, 256>>>(dstp[e], logitsb, amaxb, denb, NE * NH);
            edge_msg_kernel<<<nwb, 256>>>(srcp[e], dstp[e], logitsb, denb, vrel,
                                          outb + roff[t] * HIDC, NE);
        }

        // per-type: xs = g * (gelu(out) @ Wa + ba) + (1-g) * xs   (skip fused in epilogue)
        gelu_kernel<<<ew_grid((size_t)NALL * HIDC), 256>>>(outb, gelub, (size_t)NALL * HIDC);
        for (int t = 0; t < 3; t++) {
            size_t wofs = ((size_t)l * 3 + t) * HIDC * HIDC;
            size_t bofs = ((size_t)l * 3 + t) * HIDC;
            launch_gemm_skip(gelub + roff[t] * HIDC, Wa + wofs, ba + bofs,
                             xs + roff[t] * HIDC, cnt[t], HIDC, HIDC,
                             skp + l * 3 + t, xs + roff[t] * HIDC);
        }
    }

    // ---- output MLP: lrelu(xs @ W2 + b2), contiguous user|movie|review ----
    launch_gemm(xs, W2, b2, (float*)d_out, NALL, 128, HIDC, 1);
}

// round 15
// speedup vs baseline: 3.0283x; 1.1860x over previous
#include <cuda_runtime.h>
#include <math.h>
#include <stdint.h>

// ---------------- problem constants ----------------
#define NU   50000
#define NM   20000
#define NRV  200000
#define NALL 270000
#define HIDC 256
#define NE   200000
#define NH   8
#define HD   32
#define LRS  0.01f   // leaky relu slope

// ---------------- device scratch (no allocations allowed) ----------------
__device__ float g_xs [(size_t)NALL * HIDC];
__device__ float g_Q  [(size_t)NALL * HIDC];
__device__ float g_gelu[(size_t)NALL * HIDC];
__device__ float g_out[(size_t)NALL * HIDC];
__device__ float g_krel[(size_t)NRV * HIDC];
__device__ float g_vrel[(size_t)NRV * HIDC];
__device__ float g_logits[(size_t)NE * NH];
__device__ unsigned g_amax[(size_t)NALL * NH];
__device__ float g_den [(size_t)NALL * NH];
// combined relation-folded weights: [12][256*256], biases [12][256]
// slot z = l*3+e for K-path (0..5, includes p_rel*scale fold), 6+l*3+e for V-path
__device__ float g_wc[12 * HIDC * HIDC];
__device__ float g_bc[12 * HIDC];

__constant__ int c_styp[3] = {1, 0, 2};

// order-preserving float<->uint mapping for atomicMax on floats
__device__ __forceinline__ unsigned f2u_ord(float f) {
    unsigned u = __float_as_uint(f);
    return (u & 0x80000000u) ? ~u : (u | 0x80000000u);
}
__device__ __forceinline__ float u2f_ord(unsigned u) {
    return (u & 0x80000000u) ? __uint_as_float(u & 0x7fffffffu)
                             : __uint_as_float(~u);
}

__device__ __forceinline__ uint32_t f2tf32(float f) {
    uint32_t r;
    asm("cvt.rna.tf32.f32 %0, %1;" : "=r"(r) : "f"(f));
    return r;
}

__device__ __forceinline__ void red_add_v4(float* p, float4 v) {
    asm volatile("red.global.add.v4.f32 [%0], {%1,%2,%3,%4};"
                 :: "l"(p), "f"(v.x), "f"(v.y), "f"(v.z), "f"(v.w)
                 : "memory");
}

// ---------------- fused weight fold: all 12 slots in one launch ----------------
// slot z (blockIdx.y): z<6 -> K path (fold a_rel AND p_rel*inv_sqrt_d),
//                      z>=6 -> V path (fold m_rel only).
// WC[i, h*32+j] = sum_d Wsrc[i, h*32+d] * Arel[h][d][j] * fac(h)
// grid = (16, 12): 16 rows per block, 256 threads (thread = output column).
__global__ __launch_bounds__(256) void wcomb_all_kernel(
    const float* __restrict__ Wk, const float* __restrict__ bk,
    const float* __restrict__ Wv, const float* __restrict__ bv,
    const float* __restrict__ a_rel, const float* __restrict__ m_rel,
    const float* __restrict__ p_rel,
    float* __restrict__ WCa, float* __restrict__ bCa)
{
    __shared__ float sA[NH * HD * HD];   // 32KB
    int z = blockIdx.y;
    int isK = (z < 6);
    int le = isK ? z : z - 6;            // l*3+e
    int e = le % 3;
    int l3 = le - e;                     // l*3
    int s = c_styp[e];

    const float* Wsrc = (isK ? Wk : Wv) + (size_t)(l3 + s) * HIDC * HIDC;
    const float* bsrc = (isK ? bk : bv) + (size_t)(l3 + s) * HIDC;
    const float* Arel = (isK ? a_rel : m_rel) + (size_t)le * NH * HD * HD;
    float* WC = WCa + (size_t)z * HIDC * HIDC;
    float* bC = bCa + (size_t)z * HIDC;

    int tid = threadIdx.x;
    for (int i = tid; i < NH * HD * HD; i += 256) sA[i] = Arel[i];
    __syncthreads();

    int h = tid >> 5, j = tid & 31;
    float fac = isK ? (p_rel[(size_t)le * NH + h] * 0.17677669529663687f) : 1.0f;
    const float* Ah = &sA[h * HD * HD];
    int r0 = blockIdx.x * 16;
    for (int i = r0; i < r0 + 16; i++) {
        const float* wrow = Wsrc + (size_t)i * HIDC + h * HD;
        float acc = 0.f;
#pragma unroll
        for (int d = 0; d < HD; d++)
            acc += wrow[d] * Ah[d * HD + j];
        WC[(size_t)i * HIDC + tid] = acc * fac;
    }
    if (blockIdx.x == 0) {
        const float* brow = bsrc + h * HD;
        float acc = 0.f;
#pragma unroll
        for (int d = 0; d < HD; d++)
            acc += brow[d] * Ah[d * HD + j];
        bC[tid] = acc * fac;
    }
}

// ================= TF32 tensor-core GEMM =================
// C[M,N] = epilogue(A[M,K] * B[K,N] + bias)
// act: 0 = none, 1 = leaky relu, 2 = skip-blend (C = g*v + (1-g)*xold)
// Block tile 128x128, BK=16, 256 threads (8 warps, warp tile 32x64),
// mma.sync.m16n8k8 tf32, cp.async double-buffered smem.
// Requires N % 128 == 0, K % 16 == 0. M guarded.

#define AST 20    // As row stride (floats): conflict-free fragment loads
#define BST 136   // Bs row stride (floats): 136 mod 32 = 8 -> 8t+g distinct

__device__ __forceinline__ void load_tiles(
    float (*Asb)[AST], float (*Bsb)[BST],
    const float* __restrict__ A, const float* __restrict__ B,
    int M, int N, int K, int m0, int n0, int k0, int tid)
{
#pragma unroll
    for (int i = 0; i < 2; i++) {
        int f = tid + i * 256;
        int row = f >> 2, c4 = f & 3;
        uint32_t sm = (uint32_t)__cvta_generic_to_shared(&Asb[row][c4 * 4]);
        const float* gm = A + (size_t)(m0 + row) * K + k0 + c4 * 4;
        int v = (m0 + row < M) ? 16 : 0;
        asm volatile("cp.async.ca.shared.global [%0], [%1], 16, %2;\n"
                     :: "r"(sm), "l"(gm), "r"(v));
    }
#pragma unroll
    for (int i = 0; i < 2; i++) {
        int f = tid + i * 256;
        int row = f >> 5, c4 = f & 31;
        uint32_t sm = (uint32_t)__cvta_generic_to_shared(&Bsb[row][c4 * 4]);
        const float* gm = B + (size_t)(k0 + row) * N + n0 + c4 * 4;
        asm volatile("cp.async.cg.shared.global [%0], [%1], 16;\n"
                     :: "r"(sm), "l"(gm));
    }
}

__global__ __launch_bounds__(256, 2) void tf32gemm_kernel(
    const float* __restrict__ A, const float* __restrict__ B,
    const float* __restrict__ bias, float* __restrict__ C,
    int M, int N, int K, int act,
    const float* __restrict__ skipp, const float* __restrict__ xold)
{
    __shared__ __align__(16) float As[2][128][AST];
    __shared__ __align__(16) float Bs[2][16][BST];

    int tid  = threadIdx.x;
    int lane = tid & 31, warp = tid >> 5;
    int g = lane >> 2, t = lane & 3;
    int warpM = warp & 3, warpN = warp >> 2;
    int m0 = blockIdx.y * 128;
    int n0 = blockIdx.x * 128;

    float acc[2][8][4];
#pragma unroll
    for (int mt = 0; mt < 2; mt++)
#pragma unroll
        for (int nt = 0; nt < 8; nt++)
#pragma unroll
            for (int j = 0; j < 4; j++) acc[mt][nt][j] = 0.f;

    int nk = K >> 4;

    load_tiles(As[0], Bs[0], A, B, M, N, K, m0, n0, 0, tid);
    asm volatile("cp.async.commit_group;\n");

    for (int kt = 0; kt < nk; kt++) {
        int buf = kt & 1;
        if (kt + 1 < nk) {
            load_tiles(As[buf ^ 1], Bs[buf ^ 1], A, B, M, N, K, m0, n0,
                       (kt + 1) << 4, tid);
            asm volatile("cp.async.commit_group;\n");
            asm volatile("cp.async.wait_group 1;\n");
        } else {
            asm volatile("cp.async.wait_group 0;\n");
        }
        __syncthreads();

#pragma unroll
        for (int ks = 0; ks < 2; ks++) {
            int k0 = ks * 8;
            uint32_t af[2][4];
#pragma unroll
            for (int mt = 0; mt < 2; mt++) {
                int r = warpM * 32 + mt * 16 + g;
                af[mt][0] = f2tf32(As[buf][r][k0 + t]);
                af[mt][1] = f2tf32(As[buf][r + 8][k0 + t]);
                af[mt][2] = f2tf32(As[buf][r][k0 + t + 4]);
                af[mt][3] = f2tf32(As[buf][r + 8][k0 + t + 4]);
            }
            uint32_t bf[8][2];
#pragma unroll
            for (int nt = 0; nt < 8; nt++) {
                int c = warpN * 64 + nt * 8 + g;
                bf[nt][0] = f2tf32(Bs[buf][k0 + t][c]);
                bf[nt][1] = f2tf32(Bs[buf][k0 + t + 4][c]);
            }
#pragma unroll
            for (int mt = 0; mt < 2; mt++)
#pragma unroll
                for (int nt = 0; nt < 8; nt++)
                    asm volatile(
                        "mma.sync.aligned.m16n8k8.row.col.f32.tf32.tf32.f32 "
                        "{%0,%1,%2,%3}, {%4,%5,%6,%7}, {%8,%9}, {%0,%1,%2,%3};\n"
                        : "+f"(acc[mt][nt][0]), "+f"(acc[mt][nt][1]),
                          "+f"(acc[mt][nt][2]), "+f"(acc[mt][nt][3])
                        : "r"(af[mt][0]), "r"(af[mt][1]),
                          "r"(af[mt][2]), "r"(af[mt][3]),
                          "r"(bf[nt][0]), "r"(bf[nt][1]));
        }
        __syncthreads();
    }

    float gk = 0.f;
    if (act == 2) {
        float s = *skipp;
        gk = 1.f / (1.f + expf(-s));
    }
#pragma unroll
    for (int mt = 0; mt < 2; mt++) {
        int r0 = m0 + warpM * 32 + mt * 16 + g;
        int r1 = r0 + 8;
#pragma unroll
        for (int nt = 0; nt < 8; nt++) {
            int col = n0 + warpN * 64 + nt * 8 + t * 2;
            float bv0 = bias[col], bv1 = bias[col + 1];
            float v0 = acc[mt][nt][0] + bv0;
            float v1 = acc[mt][nt][1] + bv1;
            float v2 = acc[mt][nt][2] + bv0;
            float v3 = acc[mt][nt][3] + bv1;
            if (act == 1) {
                v0 = (v0 > 0.f) ? v0 : LRS * v0;
                v1 = (v1 > 0.f) ? v1 : LRS * v1;
                v2 = (v2 > 0.f) ? v2 : LRS * v2;
                v3 = (v3 > 0.f) ? v3 : LRS * v3;
            } else if (act == 2) {
                if (r0 < M) {
                    float2 o = *(const float2*)(xold + (size_t)r0 * N + col);
                    v0 = gk * v0 + (1.f - gk) * o.x;
                    v1 = gk * v1 + (1.f - gk) * o.y;
                }
                if (r1 < M) {
                    float2 o = *(const float2*)(xold + (size_t)r1 * N + col);
                    v2 = gk * v2 + (1.f - gk) * o.x;
                    v3 = gk * v3 + (1.f - gk) * o.y;
                }
            }
            if (r0 < M) *(float2*)(C + (size_t)r0 * N + col) = make_float2(v0, v1);
            if (r1 < M) *(float2*)(C + (size_t)r1 * N + col) = make_float2(v2, v3);
        }
    }
}

// ---------------- edge kernels ----------------
// one warp per edge; scale+p_rel already folded into krel.
// lane l: float4 group l (dims 4l..4l+3, head l>>3) and group l+32 (head 4+(l>>3)).
__global__ __launch_bounds__(256) void edge_logits_kernel(
    const int* __restrict__ src, const int* __restrict__ dst,
    const float* __restrict__ krel, const float* __restrict__ Qt,
    float* __restrict__ logits, unsigned* __restrict__ amax, int E)
{
    int e = (blockIdx.x * 256 + threadIdx.x) >> 5;
    int lane = threadIdx.x & 31;
    if (e >= E) return;
    int s = src[e], d = dst[e];
    const float4* kp = (const float4*)(krel + (size_t)s * HIDC);
    const float4* qp = (const float4*)(Qt   + (size_t)d * HIDC);

    float4 k0 = kp[lane],       q0 = qp[lane];
    float4 k1 = kp[lane + 32],  q1 = qp[lane + 32];
    float s0 = k0.x*q0.x + k0.y*q0.y + k0.z*q0.z + k0.w*q0.w;
    float s1 = k1.x*q1.x + k1.y*q1.y + k1.z*q1.z + k1.w*q1.w;
#pragma unroll
    for (int o = 4; o; o >>= 1) {
        s0 += __shfl_down_sync(0xffffffffu, s0, o);
        s1 += __shfl_down_sync(0xffffffffu, s1, o);
    }
    if ((lane & 7) == 0) {
        int h = lane >> 3;               // heads h and h+4
        logits[(size_t)e * NH + h]     = s0;
        logits[(size_t)e * NH + h + 4] = s1;
        atomicMax(&amax[(size_t)d * NH + h],     f2u_ord(s0));
        atomicMax(&amax[(size_t)d * NH + h + 4], f2u_ord(s1));
    }
}

__global__ void edge_exp_kernel(
    const int* __restrict__ dst, float* __restrict__ logits,
    const unsigned* __restrict__ amax, float* __restrict__ den, int total)
{
    int i = blockIdx.x * blockDim.x + threadIdx.x;
    if (i >= total) return;
    int e = i >> 3, h = i & 7;
    int d = dst[e];
    float m  = u2f_ord(amax[(size_t)d * NH + h]);
    float ex = expf(logits[i] - m);
    logits[i] = ex;
    atomicAdd(&den[(size_t)d * NH + h], ex);
}

// one warp per edge; lane l handles float4 groups l (head l>>3) and l+32 (head 4+(l>>3))
__global__ __launch_bounds__(256) void edge_msg_kernel(
    const int* __restrict__ src, const int* __restrict__ dst,
    const float* __restrict__ logits, const float* __restrict__ den,
    const float* __restrict__ vrel, float* __restrict__ outt, int E)
{
    int e = (blockIdx.x * 256 + threadIdx.x) >> 5;
    int lane = threadIdx.x & 31;
    if (e >= E) return;
    int s = src[e], d = dst[e];
    int h0 = lane >> 3, h1 = h0 + 4;
    float c0 = logits[(size_t)e * NH + h0] / (den[(size_t)d * NH + h0] + 1e-16f);
    float c1 = logits[(size_t)e * NH + h1] / (den[(size_t)d * NH + h1] + 1e-16f);
    const float4* vp = (const float4*)(vrel + (size_t)s * HIDC);
    float* op = outt + (size_t)d * HIDC;
    float4 v0 = vp[lane], v1 = vp[lane + 32];
    red_add_v4(op + lane * 4,
               make_float4(v0.x * c0, v0.y * c0, v0.z * c0, v0.w * c0));
    red_add_v4(op + 128 + lane * 4,
               make_float4(v1.x * c1, v1.y * c1, v1.z * c1, v1.w * c1));
}

// ---------------- elementwise ----------------
__global__ void fill_kernel(float* p, float v, size_t n) {
    size_t i = (size_t)blockIdx.x * blockDim.x + threadIdx.x;
    size_t stride = (size_t)gridDim.x * blockDim.x;
    for (; i < n; i += stride) p[i] = v;
}

__global__ void gelu_kernel(const float* __restrict__ in, float* __restrict__ out, size_t n) {
    size_t i = (size_t)blockIdx.x * blockDim.x + threadIdx.x;
    size_t stride = (size_t)gridDim.x * blockDim.x;
    for (; i < n; i += stride) {
        float x = in[i];
        out[i] = 0.5f * x * (1.f + erff(x * 0.70710678118654752f));
    }
}

// ---------------- host orchestration ----------------
static void launch_gemm(const float* A, const float* B, const float* bias, float* C,
                        int M, int N, int K, int act) {
    dim3 grid(N / 128, (M + 127) / 128);
    tf32gemm_kernel<<<grid, 256>>>(A, B, bias, C, M, N, K, act, nullptr, nullptr);
}

static void launch_gemm_skip(const float* A, const float* B, const float* bias, float* C,
                             int M, int N, int K, const float* skipp, const float* xold) {
    dim3 grid(N / 128, (M + 127) / 128);
    tf32gemm_kernel<<<grid, 256>>>(A, B, bias, C, M, N, K, 2, skipp, xold);
}

static inline int ew_grid(size_t n) {
    size_t b = (n + 255) / 256;
    return (int)(b > 16384 ? 16384 : b);
}

extern "C" void kernel_launch(void* const* d_in, const int* in_sizes, int n_in,
                              void* d_out, int out_size)
{
    (void)in_sizes; (void)n_in; (void)out_size;

    const float* x_user   = (const float*)d_in[0];
    const float* x_movie  = (const float*)d_in[1];
    const float* x_review = (const float*)d_in[2];
    const int*  srcp[3] = {(const int*)d_in[3], (const int*)d_in[5], (const int*)d_in[7]};
    const int*  dstp[3] = {(const int*)d_in[4], (const int*)d_in[6], (const int*)d_in[8]};
    const float* W1 = (const float*)d_in[9];
    const float* b1 = (const float*)d_in[10];
    const float* W2 = (const float*)d_in[11];
    const float* b2 = (const float*)d_in[12];
    const float* Wk = (const float*)d_in[13];
    const float* bk = (const float*)d_in[14];
    const float* Wq = (const float*)d_in[15];
    const float* bq = (const float*)d_in[16];
    const float* Wv = (const float*)d_in[17];
    const float* bv = (const float*)d_in[18];
    const float* Wa = (const float*)d_in[19];
    const float* ba = (const float*)d_in[20];
    const float* skp   = (const float*)d_in[21];
    const float* a_rel = (const float*)d_in[22];
    const float* m_rel = (const float*)d_in[23];
    const float* p_rel = (const float*)d_in[24];

    float *xs, *Qb, *gelub, *outb, *krel, *vrel, *logitsb, *denb, *wc, *bc;
    unsigned* amaxb;
    cudaGetSymbolAddress((void**)&xs,     g_xs);
    cudaGetSymbolAddress((void**)&Qb,     g_Q);
    cudaGetSymbolAddress((void**)&gelub,  g_gelu);
    cudaGetSymbolAddress((void**)&outb,   g_out);
    cudaGetSymbolAddress((void**)&krel,   g_krel);
    cudaGetSymbolAddress((void**)&vrel,   g_vrel);
    cudaGetSymbolAddress((void**)&logitsb,g_logits);
    cudaGetSymbolAddress((void**)&amaxb,  g_amax);
    cudaGetSymbolAddress((void**)&denb,   g_den);
    cudaGetSymbolAddress((void**)&wc,     g_wc);
    cudaGetSymbolAddress((void**)&bc,     g_bc);

    const int    cnt[3]  = {NU, NM, NRV};
    const size_t roff[3] = {0, (size_t)NU, (size_t)NU + NM};
    const int styp[3] = {1, 0, 2};
    const int dtyp[3] = {2, 2, 0};

    // ---- fold relation matrices (+ p_rel*scale for K) into weights: ONE launch ----
    {
        dim3 grid(16, 12);
        wcomb_all_kernel<<<grid, 256>>>(Wk, bk, Wv, bv, a_rel, m_rel, p_rel, wc, bc);
    }

    // ---- input MLP: xs[t] = lrelu(x_t @ W1 + b1) ----
    launch_gemm(x_user,   W1, b1, xs + roff[0] * HIDC, NU,  HIDC, 768, 1);
    launch_gemm(x_movie,  W1, b1, xs + roff[1] * HIDC, NM,  HIDC, 768, 1);
    launch_gemm(x_review, W1, b1, xs + roff[2] * HIDC, NRV, HIDC, 768, 1);

    for (int l = 0; l < 2; l++) {
        // Q projections (only dst types 0 and 2 are ever destinations)
        for (int ti = 0; ti < 2; ti++) {
            int t = (ti == 0) ? 0 : 2;
            size_t wofs = ((size_t)l * 3 + t) * HIDC * HIDC;
            size_t bofs = ((size_t)l * 3 + t) * HIDC;
            launch_gemm(xs + roff[t] * HIDC, Wq + wofs, bq + bofs, Qb + roff[t] * HIDC,
                        cnt[t], HIDC, HIDC, 0);
        }

        // zero attention accumulators
        fill_kernel<<<ew_grid((size_t)NALL * HIDC), 256>>>(outb, 0.f, (size_t)NALL * HIDC);

        for (int e = 0; e < 3; e++) {
            int s = styp[e], t = dtyp[e];
            int cK = l * 3 + e, cV = 6 + l * 3 + e;

            // relation-folded K and V projections (straight into krel/vrel)
            launch_gemm(xs + roff[s] * HIDC, wc + (size_t)cK * HIDC * HIDC,
                        bc + (size_t)cK * HIDC, krel, cnt[s], HIDC, HIDC, 0);
            launch_gemm(xs + roff[s] * HIDC, wc + (size_t)cV * HIDC * HIDC,
                        bc + (size_t)cV * HIDC, vrel, cnt[s], HIDC, HIDC, 0);

            fill_kernel<<<ew_grid((size_t)cnt[t] * NH), 256>>>((float*)amaxb, 0.f, (size_t)cnt[t] * NH);
            fill_kernel<<<ew_grid((size_t)cnt[t] * NH), 256>>>(denb, 0.f, (size_t)cnt[t] * NH);

            int nwb = (NE + 7) / 8;   // 8 warps/block, 1 warp/edge
            edge_logits_kernel<<<nwb, 256>>>(srcp[e], dstp[e], krel, Qb + roff[t] * HIDC,
                                             logitsb, amaxb, NE);
            edge_exp_kernel<<<(NE * NH + 255) / 256, 256>>>(dstp[e], logitsb, amaxb, denb, NE * NH);
            edge_msg_kernel<<<nwb, 256>>>(srcp[e], dstp[e], logitsb, denb, vrel,
                                          outb + roff[t] * HIDC, NE);
        }

        // per-type: xs = g * (gelu(out) @ Wa + ba) + (1-g) * xs   (skip fused in epilogue)
        gelu_kernel<<<ew_grid((size_t)NALL * HIDC), 256>>>(outb, gelub, (size_t)NALL * HIDC);
        for (int t = 0; t < 3; t++) {
            size_t wofs = ((size_t)l * 3 + t) * HIDC * HIDC;
            size_t bofs = ((size_t)l * 3 + t) * HIDC;
            launch_gemm_skip(gelub + roff[t] * HIDC, Wa + wofs, ba + bofs,
                             xs + roff[t] * HIDC, cnt[t], HIDC, HIDC,
                             skp + l * 3 + t, xs + roff[t] * HIDC);
        }
    }

    // ---- output MLP: lrelu(xs @ W2 + b2), contiguous user|movie|review ----
    launch_gemm(xs, W2, b2, (float*)d_out, NALL, 128, HIDC, 1);
}